// round 5
// baseline (speedup 1.0000x reference)
#include <cuda_runtime.h>
#include <math.h>

#define NQ 300
#define NF 8
#define BS 2
#define HW 96
#define HWHW 9216
#define D_TOT 73728.0f   // NF*H*W

// Scratch (static __device__ — no allocation)
__device__ float g_focal [BS*NF*NQ];
__device__ float g_ssum  [BS*NF*NQ];
__device__ float g_stsum [BS*NF*NQ];
__device__ float g_colmax[BS*NF*NQ*HW];  // src_y pieces: max over h
__device__ float g_rowmax[BS*NF*NQ*HW];  // src_x pieces: max over w
__device__ float g_tcolmax[BS*NF*HW];
__device__ float g_trowmax[BS*NF*HW];
__device__ float g_tsum  [BS*NF];

// ---------------------------------------------------------------------------
// Heavy kernel: one block per (b,f,q) 96x96 mask tile.
// Computes focal-loss sum, sigma sums for dice, and row/col maxes for proj.
// ---------------------------------------------------------------------------
__global__ __launch_bounds__(256) void mask_heavy(
    const float* __restrict__ masks, const float* __restrict__ tmask,
    const unsigned char* __restrict__ vpad)
{
    const int blk = blockIdx.x;          // ((b*NF+f)*NQ + q)
    const int bf  = blk / NQ;            // b*NF + f
    const int b   = bf / NF;
    const float* __restrict__ X  = masks + (size_t)blk * HWHW;
    const float* __restrict__ T  = tmask + (size_t)bf  * HWHW;
    const unsigned char* __restrict__ VP = vpad + (size_t)b * HWHW;

    const int warp = threadIdx.x >> 5;
    const int lane = threadIdx.x & 31;

    __shared__ float rowmax_s[HW];
    __shared__ float colw[8][HW];
    __shared__ float red[8][3];

    float facc = 0.f, sacc = 0.f, stacc = 0.f;
    float cm0 = -1e30f, cm1 = -1e30f, cm2 = -1e30f;

    for (int h = warp; h < HW; h += 8) {
        const int base = h * HW;
        float rm = -1e30f;
        #pragma unroll
        for (int p = 0; p < 3; p++) {
            const int w = lane + 32*p;
            float x = X[base + w];
            if (VP[base + w]) x = 0.f;
            const float t = T[base + w];

            const float a   = fabsf(x);
            const float e   = __expf(-a);          // exp(-|x|)
            const float ope = 1.f + e;
            const float lp  = __logf(ope);         // log1p(exp(-|x|))
            const float r   = __fdividef(1.f, ope);
            const float v   = e * r;
            const bool  xpos = (x >= 0.f);
            const float s    = xpos ? r : v;       // sigmoid(x)
            const float oms  = xpos ? v : r;       // 1 - sigmoid(x)
            const float spb  = a + lp;
            const float sp_pos = xpos ? spb : lp;  // softplus(x)
            const float sp_neg = xpos ? lp  : spb; // softplus(-x)
            const float f1 = 0.25f * sp_neg * (oms*oms);
            const float f0 = 0.75f * sp_pos * (s*s);
            const bool  tt = (t != 0.f);

            facc  += tt ? f1 : f0;
            sacc  += s;
            stacc += tt ? s : 0.f;
            rm = fmaxf(rm, x);
            if (p == 0) cm0 = fmaxf(cm0, x);
            else if (p == 1) cm1 = fmaxf(cm1, x);
            else cm2 = fmaxf(cm2, x);
        }
        #pragma unroll
        for (int off = 16; off; off >>= 1)
            rm = fmaxf(rm, __shfl_xor_sync(0xffffffffu, rm, off));
        if (lane == 0) rowmax_s[h] = rm;  // each h owned by exactly one warp
    }

    colw[warp][lane]      = cm0;
    colw[warp][lane + 32] = cm1;
    colw[warp][lane + 64] = cm2;

    #pragma unroll
    for (int off = 16; off; off >>= 1) {
        facc  += __shfl_xor_sync(0xffffffffu, facc,  off);
        sacc  += __shfl_xor_sync(0xffffffffu, sacc,  off);
        stacc += __shfl_xor_sync(0xffffffffu, stacc, off);
    }
    if (lane == 0) { red[warp][0] = facc; red[warp][1] = sacc; red[warp][2] = stacc; }
    __syncthreads();

    if (threadIdx.x == 0) {
        float a = 0.f, s = 0.f, c = 0.f;
        #pragma unroll
        for (int i = 0; i < 8; i++) { a += red[i][0]; s += red[i][1]; c += red[i][2]; }
        g_focal[blk] = a; g_ssum[blk] = s; g_stsum[blk] = c;
    }
    if (threadIdx.x < HW) {
        float m = colw[0][threadIdx.x];
        #pragma unroll
        for (int i = 1; i < 8; i++) m = fmaxf(m, colw[i][threadIdx.x]);
        g_colmax[(size_t)blk * HW + threadIdx.x] = m;
        g_rowmax[(size_t)blk * HW + threadIdx.x] = rowmax_s[threadIdx.x];
    }
}

// ---------------------------------------------------------------------------
// Target-side precompute: per (b,f) row/col maxes of tmask + sum(tmask).
// ---------------------------------------------------------------------------
__global__ __launch_bounds__(96) void tgt_kernel(const float* __restrict__ tmask)
{
    const int bf = blockIdx.x;
    const float* __restrict__ T = tmask + (size_t)bf * HWHW;
    const int i = threadIdx.x;      // 0..95
    float cmax = -1e30f, rmax = -1e30f, rs = 0.f;
    for (int h = 0; h < HW; h++) cmax = fmaxf(cmax, T[h*HW + i]);
    for (int w = 0; w < HW; w++) { float v = T[i*HW + w]; rmax = fmaxf(rmax, v); rs += v; }
    g_tcolmax[bf*HW + i] = cmax;
    g_trowmax[bf*HW + i] = rmax;

    __shared__ float sred[3];
    const int lane = i & 31, warp = i >> 5;
    #pragma unroll
    for (int off = 16; off; off >>= 1) rs += __shfl_xor_sync(0xffffffffu, rs, off);
    if (lane == 0) sred[warp] = rs;
    __syncthreads();
    if (i == 0) g_tsum[bf] = sred[0] + sred[1] + sred[2];
}

// ---------------------------------------------------------------------------
// Combine: per (b,q) block — proj dice over 768 maxes + class/bbox/giou + C.
// ---------------------------------------------------------------------------
__global__ __launch_bounds__(128) void combine_kernel(
    const float* __restrict__ logits, const float* __restrict__ boxes,
    const float* __restrict__ tboxes, const int* __restrict__ tvalid,
    float* __restrict__ out)
{
    const int bq = blockIdx.x;
    const int b  = bq / NQ;
    const int q  = bq % NQ;
    const int tid = threadIdx.x, lane = tid & 31, warp = tid >> 5;

    float v0 = 0.f, v1 = 0.f, v2 = 0.f, v3 = 0.f, v4 = 0.f, v5 = 0.f;
    for (int j = tid; j < NF*HW; j += 128) {
        const int f = j / HW, k = j % HW;
        const int src  = ((b*NF + f)*NQ + q)*HW + k;
        const int tsrc = (b*NF + f)*HW + k;
        const float ym = g_colmax[src];
        const float ty = g_tcolmax[tsrc];
        const float sy = __fdividef(1.f, 1.f + __expf(-ym));
        v0 += sy; v1 += (ty != 0.f) ? sy : 0.f; v2 += ty;
        const float xm = g_rowmax[src];
        const float tx = g_trowmax[tsrc];
        const float sx = __fdividef(1.f, 1.f + __expf(-xm));
        v3 += sx; v4 += (tx != 0.f) ? sx : 0.f; v5 += tx;
    }
    __shared__ float red[4][6];
    float v[6] = {v0, v1, v2, v3, v4, v5};
    #pragma unroll
    for (int off = 16; off; off >>= 1)
        #pragma unroll
        for (int m = 0; m < 6; m++) v[m] += __shfl_xor_sync(0xffffffffu, v[m], off);
    if (lane == 0)
        #pragma unroll
        for (int m = 0; m < 6; m++) red[warp][m] = v[m];
    __syncthreads();

    if (tid == 0) {
        float S[6];
        #pragma unroll
        for (int m = 0; m < 6; m++) S[m] = red[0][m] + red[1][m] + red[2][m] + red[3][m];

        float focal = 0.f, ss = 0.f, st = 0.f, ts = 0.f;
        #pragma unroll
        for (int f = 0; f < NF; f++) {
            const int idx = (b*NF + f)*NQ + q;
            focal += g_focal[idx]; ss += g_ssum[idx]; st += g_stsum[idx];
            ts += g_tsum[b*NF + f];
        }
        const float cost_mask = focal / D_TOT;
        const float cost_dice = -(2.f*st + 1.f) / (ss + ts + 1.f);
        const float dice_y = (2.f*S[1] + 1.f) / (S[0] + S[2] + 1.f);
        const float dice_x = (2.f*S[4] + 1.f) / (S[3] + S[5] + 1.f);
        const float cost_proj = -0.5f * (dice_y + dice_x);

        float cls = 0.f, wsum = 0.f, cb = 0.f, cg = 0.f;
        for (int f = 0; f < NF; f++) {
            const int bi = (b*NF + f)*NQ + q;
            const float lg = logits[bi];
            const float p  = __fdividef(1.f, 1.f + __expf(-lg));
            const float neg = 0.75f * p * p * (-__logf(1.f - p + 1e-8f));
            const float pos = 0.25f * (1.f - p) * (1.f - p) * (-__logf(p + 1e-8f));
            const float w = (tvalid[b*NF + f] != 0) ? 1.f : 0.f;
            cls += w * (pos - neg); wsum += w;

            const float* sb = boxes  + (size_t)bi * 4;
            const float* tb = tboxes + (size_t)(b*NF + f) * 4;
            cb += fabsf(sb[0]-tb[0]) + fabsf(sb[1]-tb[1])
                + fabsf(sb[2]-tb[2]) + fabsf(sb[3]-tb[3]);

            const float sx0 = sb[0] - 0.5f*sb[2], sy0 = sb[1] - 0.5f*sb[3];
            const float sx1 = sb[0] + 0.5f*sb[2], sy1 = sb[1] + 0.5f*sb[3];
            const float tx0 = tb[0] - 0.5f*tb[2], ty0 = tb[1] - 0.5f*tb[3];
            const float tx1 = tb[0] + 0.5f*tb[2], ty1 = tb[1] + 0.5f*tb[3];
            const float a1 = (sx1 - sx0) * (sy1 - sy0);
            const float a2 = (tx1 - tx0) * (ty1 - ty0);
            float iw = fminf(sx1, tx1) - fmaxf(sx0, tx0); iw = fmaxf(iw, 0.f);
            float ih = fminf(sy1, ty1) - fmaxf(sy0, ty0); ih = fmaxf(ih, 0.f);
            const float inter = iw * ih;
            const float uni = a1 + a2 - inter;
            const float iou = inter / uni;
            float cw = fmaxf(sx1, tx1) - fminf(sx0, tx0); cw = fmaxf(cw, 0.f);
            float ch = fmaxf(sy1, ty1) - fminf(sy0, ty0); ch = fmaxf(ch, 0.f);
            const float areac = cw * ch;
            const float giou = iou - (areac - uni) / areac;
            cg += -giou;
        }
        const float cost_class = cls / wsum;
        const float cost_bbox  = cb * (1.f / (float)NF);
        const float cost_giou  = cg * (1.f / (float)NF);

        out[bq] = cost_class + cost_bbox + cost_giou + cost_mask + cost_dice + cost_proj;
    }
}

// ---------------------------------------------------------------------------
// Argmin over q per batch (first-occurrence tie-break), write indices.
// ---------------------------------------------------------------------------
__global__ void argmin_kernel(float* __restrict__ out)
{
    const int b = threadIdx.x >> 5;
    const int lane = threadIdx.x & 31;
    if (b >= BS) return;
    float best = 3.4e38f;
    int bi = NQ;
    for (int q = lane; q < NQ; q += 32) {
        const float v = out[b*NQ + q];
        if (v < best) { best = v; bi = q; }   // strided keeps earliest per lane
    }
    #pragma unroll
    for (int off = 16; off; off >>= 1) {
        const float ov = __shfl_xor_sync(0xffffffffu, best, off);
        const int   oi = __shfl_xor_sync(0xffffffffu, bi,   off);
        if (ov < best || (ov == best && oi < bi)) { best = ov; bi = oi; }
    }
    if (lane == 0) {
        out[BS*NQ + b]      = (float)bi;  // src_ind
        out[BS*NQ + BS + b] = 0.f;        // tgt_ind
    }
}

extern "C" void kernel_launch(void* const* d_in, const int* in_sizes, int n_in,
                              void* d_out, int out_size)
{
    const float* logits = (const float*)d_in[0];  // (2,8,300,1)
    const float* boxes  = (const float*)d_in[1];  // (2,8,300,4)
    const float* masks  = (const float*)d_in[2];  // (2,8,300,96,96)
    const float* tmask  = (const float*)d_in[3];  // (2,8,96,96)
    const float* tboxes = (const float*)d_in[4];  // (2,8,4)
    const int*   tvalid = (const int*)d_in[5];    // (2,8)
    const unsigned char* vpad = (const unsigned char*)d_in[6];  // (2,96,96) bool
    float* out = (float*)d_out;                   // 600 C + 2 src + 2 tgt

    mask_heavy<<<BS*NF*NQ, 256>>>(masks, tmask, vpad);
    tgt_kernel<<<BS*NF, 96>>>(tmask);
    combine_kernel<<<BS*NQ, 128>>>(logits, boxes, tboxes, tvalid, out);
    argmin_kernel<<<1, 64>>>(out);
}

// round 9
// speedup vs baseline: 1.2705x; 1.2705x over previous
#include <cuda_runtime.h>
#include <math.h>

#define NQ 300
#define NF 8
#define BS 2
#define HW 96
#define HWHW 9216
#define D_TOT 73728.0f   // NF*H*W

// Scratch (static __device__ — no allocation)
__device__ float g_focal [BS*NF*NQ];
__device__ float g_ssum  [BS*NF*NQ];
__device__ float g_stsum [BS*NF*NQ];
__device__ float g_colmax[BS*NF*NQ*HW];  // src_y pieces: max over h
__device__ float g_rowmax[BS*NF*NQ*HW];  // src_x pieces: max over w
__device__ float g_tcolmax[BS*NF*HW];
__device__ float g_trowmax[BS*NF*HW];
__device__ float g_tsum  [BS*NF];
__device__ uint4 g_tbits [BS*NF*HW];     // per-(b,f) row bitmask of (t!=0)
__device__ uint4 g_vbits [BS*HW];        // per-b row bitmask of valid_pad

// ---------------------------------------------------------------------------
// Prep: per (b,f) target row/col maxes, sum, and t-bitmasks; per-b vpad bits.
// grid = BS*NF + BS, block = 96 (thread i = row/col index)
// ---------------------------------------------------------------------------
__global__ __launch_bounds__(96) void prep_kernel(
    const float* __restrict__ tmask, const unsigned char* __restrict__ vpad)
{
    const int i = threadIdx.x;
    if (blockIdx.x < BS*NF) {
        const int bf = blockIdx.x;
        const float* __restrict__ T = tmask + (size_t)bf * HWHW;
        float cmax = -1e30f, rmax = -1e30f, rs = 0.f;
        unsigned bm[3] = {0u, 0u, 0u};
        for (int h = 0; h < HW; h++) cmax = fmaxf(cmax, T[h*HW + i]);
        for (int w = 0; w < HW; w++) {
            const float v = T[i*HW + w];
            rmax = fmaxf(rmax, v); rs += v;
            if (v != 0.f) bm[w >> 5] |= (1u << (w & 31));
        }
        g_tcolmax[bf*HW + i] = cmax;
        g_trowmax[bf*HW + i] = rmax;
        g_tbits[bf*HW + i] = make_uint4(bm[0], bm[1], bm[2], 0u);

        __shared__ float sred[3];
        const int lane = i & 31, warp = i >> 5;
        #pragma unroll
        for (int off = 16; off; off >>= 1) rs += __shfl_xor_sync(0xffffffffu, rs, off);
        if (lane == 0) sred[warp] = rs;
        __syncthreads();
        if (i == 0) g_tsum[bf] = sred[0] + sred[1] + sred[2];
    } else {
        const int b = blockIdx.x - BS*NF;
        const unsigned char* __restrict__ VP = vpad + (size_t)b * HWHW;
        unsigned bm[3] = {0u, 0u, 0u};
        for (int w = 0; w < HW; w++)
            if (VP[i*HW + w]) bm[w >> 5] |= (1u << (w & 31));
        g_vbits[b*HW + i] = make_uint4(bm[0], bm[1], bm[2], 0u);
    }
}

// ---------------------------------------------------------------------------
// Heavy kernel: one block per (b,f,q) 96x96 mask tile.
// Per element: z = t ? -x : x;  focal = c*softplus(z)*sigmoid(z)^2,
// A += sigmoid(z); B += t?sigmoid(z):0.  Then  sum(s)=A+ts-2B, sum(s*t)=ts-B.
// ---------------------------------------------------------------------------
__global__ __launch_bounds__(256) void mask_heavy(const float* __restrict__ masks)
{
    const int blk = blockIdx.x;          // ((b*NF+f)*NQ + q)
    const int bf  = blk / NQ;            // b*NF + f
    const int b   = bf / NF;
    const float* __restrict__ X = masks + (size_t)blk * HWHW;

    const int warp = threadIdx.x >> 5;
    const int lane = threadIdx.x & 31;
    const unsigned lanebit = 1u << lane;

    __shared__ float rowmax_s[HW];
    __shared__ float colw[8][HW];
    __shared__ float red[8][3];

    float facc = 0.f, aacc = 0.f, bacc = 0.f;
    float cm0 = -1e30f, cm1 = -1e30f, cm2 = -1e30f;

    for (int h = warp; h < HW; h += 8) {
        const int base = h * HW;
        const uint4 tb = g_tbits[bf*HW + h];   // uniform -> broadcast load
        const uint4 vb = g_vbits[b *HW + h];
        const unsigned tw[3] = {tb.x, tb.y, tb.z};
        const unsigned vw[3] = {vb.x, vb.y, vb.z};
        float rm = -1e30f;
        #pragma unroll
        for (int p = 0; p < 3; p++) {
            const bool tt = (tw[p] & lanebit) != 0u;
            const bool vz = (vw[p] & lanebit) != 0u;
            float x = X[base + lane + 32*p];
            if (vz) x = 0.f;
            const float z   = tt ? -x : x;
            const float e   = __expf(z);           // |z| <= ~10, safe
            const float ope = 1.f + e;
            const float sg  = e * __fdividef(1.f, ope);   // sigmoid(z)
            const float sp  = __logf(ope);                // softplus(z)
            const float c   = tt ? 0.25f : 0.75f;
            facc = fmaf(c, sp * sg * sg, facc);
            aacc += sg;
            if (tt) bacc += sg;
            rm = fmaxf(rm, x);
            if      (p == 0) cm0 = fmaxf(cm0, x);
            else if (p == 1) cm1 = fmaxf(cm1, x);
            else             cm2 = fmaxf(cm2, x);
        }
        #pragma unroll
        for (int off = 16; off; off >>= 1)
            rm = fmaxf(rm, __shfl_xor_sync(0xffffffffu, rm, off));
        if (lane == 0) rowmax_s[h] = rm;  // each h owned by exactly one warp
    }

    colw[warp][lane]      = cm0;
    colw[warp][lane + 32] = cm1;
    colw[warp][lane + 64] = cm2;

    #pragma unroll
    for (int off = 16; off; off >>= 1) {
        facc += __shfl_xor_sync(0xffffffffu, facc, off);
        aacc += __shfl_xor_sync(0xffffffffu, aacc, off);
        bacc += __shfl_xor_sync(0xffffffffu, bacc, off);
    }
    if (lane == 0) { red[warp][0] = facc; red[warp][1] = aacc; red[warp][2] = bacc; }
    __syncthreads();

    if (threadIdx.x == 0) {
        float F = 0.f, A = 0.f, B = 0.f;
        #pragma unroll
        for (int i = 0; i < 8; i++) { F += red[i][0]; A += red[i][1]; B += red[i][2]; }
        const float ts = g_tsum[bf];
        g_focal[blk] = F;
        g_ssum [blk] = A + ts - 2.f*B;   // sum over pixels of sigmoid(x)
        g_stsum[blk] = ts - B;           // sum over pixels of sigmoid(x)*t
    }
    if (threadIdx.x < HW) {
        float m = colw[0][threadIdx.x];
        #pragma unroll
        for (int i = 1; i < 8; i++) m = fmaxf(m, colw[i][threadIdx.x]);
        g_colmax[(size_t)blk * HW + threadIdx.x] = m;
        g_rowmax[(size_t)blk * HW + threadIdx.x] = rowmax_s[threadIdx.x];
    }
}

// ---------------------------------------------------------------------------
// Combine: per (b,q) block — proj dice over 768 maxes + class/bbox/giou + C.
// ---------------------------------------------------------------------------
__global__ __launch_bounds__(128) void combine_kernel(
    const float* __restrict__ logits, const float* __restrict__ boxes,
    const float* __restrict__ tboxes, const int* __restrict__ tvalid,
    float* __restrict__ out)
{
    const int bq = blockIdx.x;
    const int b  = bq / NQ;
    const int q  = bq % NQ;
    const int tid = threadIdx.x, lane = tid & 31, warp = tid >> 5;

    float v0 = 0.f, v1 = 0.f, v2 = 0.f, v3 = 0.f, v4 = 0.f, v5 = 0.f;
    for (int j = tid; j < NF*HW; j += 128) {
        const int f = j / HW, k = j % HW;
        const int src  = ((b*NF + f)*NQ + q)*HW + k;
        const int tsrc = (b*NF + f)*HW + k;
        const float ym = g_colmax[src];
        const float ty = g_tcolmax[tsrc];
        const float sy = __fdividef(1.f, 1.f + __expf(-ym));
        v0 += sy; v1 += (ty != 0.f) ? sy : 0.f; v2 += ty;
        const float xm = g_rowmax[src];
        const float tx = g_trowmax[tsrc];
        const float sx = __fdividef(1.f, 1.f + __expf(-xm));
        v3 += sx; v4 += (tx != 0.f) ? sx : 0.f; v5 += tx;
    }
    __shared__ float red[4][6];
    float v[6] = {v0, v1, v2, v3, v4, v5};
    #pragma unroll
    for (int off = 16; off; off >>= 1)
        #pragma unroll
        for (int m = 0; m < 6; m++) v[m] += __shfl_xor_sync(0xffffffffu, v[m], off);
    if (lane == 0)
        #pragma unroll
        for (int m = 0; m < 6; m++) red[warp][m] = v[m];
    __syncthreads();

    if (tid == 0) {
        float S[6];
        #pragma unroll
        for (int m = 0; m < 6; m++) S[m] = red[0][m] + red[1][m] + red[2][m] + red[3][m];

        float focal = 0.f, ss = 0.f, st = 0.f, ts = 0.f;
        #pragma unroll
        for (int f = 0; f < NF; f++) {
            const int idx = (b*NF + f)*NQ + q;
            focal += g_focal[idx]; ss += g_ssum[idx]; st += g_stsum[idx];
            ts += g_tsum[b*NF + f];
        }
        const float cost_mask = focal / D_TOT;
        const float cost_dice = -(2.f*st + 1.f) / (ss + ts + 1.f);
        const float dice_y = (2.f*S[1] + 1.f) / (S[0] + S[2] + 1.f);
        const float dice_x = (2.f*S[4] + 1.f) / (S[3] + S[5] + 1.f);
        const float cost_proj = -0.5f * (dice_y + dice_x);

        float cls = 0.f, wsum = 0.f, cb = 0.f, cg = 0.f;
        for (int f = 0; f < NF; f++) {
            const int bi = (b*NF + f)*NQ + q;
            const float lg = logits[bi];
            const float p  = __fdividef(1.f, 1.f + __expf(-lg));
            const float neg = 0.75f * p * p * (-__logf(1.f - p + 1e-8f));
            const float pos = 0.25f * (1.f - p) * (1.f - p) * (-__logf(p + 1e-8f));
            const float w = (tvalid[b*NF + f] != 0) ? 1.f : 0.f;
            cls += w * (pos - neg); wsum += w;

            const float* sb = boxes  + (size_t)bi * 4;
            const float* tb = tboxes + (size_t)(b*NF + f) * 4;
            cb += fabsf(sb[0]-tb[0]) + fabsf(sb[1]-tb[1])
                + fabsf(sb[2]-tb[2]) + fabsf(sb[3]-tb[3]);

            const float sx0 = sb[0] - 0.5f*sb[2], sy0 = sb[1] - 0.5f*sb[3];
            const float sx1 = sb[0] + 0.5f*sb[2], sy1 = sb[1] + 0.5f*sb[3];
            const float tx0 = tb[0] - 0.5f*tb[2], ty0 = tb[1] - 0.5f*tb[3];
            const float tx1 = tb[0] + 0.5f*tb[2], ty1 = tb[1] + 0.5f*tb[3];
            const float a1 = (sx1 - sx0) * (sy1 - sy0);
            const float a2 = (tx1 - tx0) * (ty1 - ty0);
            float iw = fminf(sx1, tx1) - fmaxf(sx0, tx0); iw = fmaxf(iw, 0.f);
            float ih = fminf(sy1, ty1) - fmaxf(sy0, ty0); ih = fmaxf(ih, 0.f);
            const float inter = iw * ih;
            const float uni = a1 + a2 - inter;
            const float iou = inter / uni;
            float cw = fmaxf(sx1, tx1) - fminf(sx0, tx0); cw = fmaxf(cw, 0.f);
            float ch = fmaxf(sy1, ty1) - fminf(sy0, ty0); ch = fmaxf(ch, 0.f);
            const float areac = cw * ch;
            const float giou = iou - (areac - uni) / areac;
            cg += -giou;
        }
        const float cost_class = cls / wsum;
        const float cost_bbox  = cb * (1.f / (float)NF);
        const float cost_giou  = cg * (1.f / (float)NF);

        out[bq] = cost_class + cost_bbox + cost_giou + cost_mask + cost_dice + cost_proj;
    }
}

// ---------------------------------------------------------------------------
// Argmin over q per batch (first-occurrence tie-break), write indices.
// Batched prefetch (MLP=10) to avoid serial L2 latency chains.
// ---------------------------------------------------------------------------
__global__ void argmin_kernel(float* __restrict__ out)
{
    const int b = threadIdx.x >> 5;
    const int lane = threadIdx.x & 31;
    if (b >= BS) return;
    float v[10];
    #pragma unroll
    for (int i = 0; i < 10; i++) {
        const int q = lane + 32*i;
        v[i] = (q < NQ) ? out[b*NQ + q] : 3.4e38f;
    }
    float best = 3.4e38f;
    int bi = NQ;
    #pragma unroll
    for (int i = 0; i < 10; i++) {
        if (v[i] < best) { best = v[i]; bi = lane + 32*i; }  // ascending i keeps earliest
    }
    #pragma unroll
    for (int off = 16; off; off >>= 1) {
        const float ov = __shfl_xor_sync(0xffffffffu, best, off);
        const int   oi = __shfl_xor_sync(0xffffffffu, bi,   off);
        if (ov < best || (ov == best && oi < bi)) { best = ov; bi = oi; }
    }
    if (lane == 0) {
        out[BS*NQ + b]      = (float)bi;  // src_ind
        out[BS*NQ + BS + b] = 0.f;        // tgt_ind
    }
}

extern "C" void kernel_launch(void* const* d_in, const int* in_sizes, int n_in,
                              void* d_out, int out_size)
{
    const float* logits = (const float*)d_in[0];  // (2,8,300,1)
    const float* boxes  = (const float*)d_in[1];  // (2,8,300,4)
    const float* masks  = (const float*)d_in[2];  // (2,8,300,96,96)
    const float* tmask  = (const float*)d_in[3];  // (2,8,96,96)
    const float* tboxes = (const float*)d_in[4];  // (2,8,4)
    const int*   tvalid = (const int*)d_in[5];    // (2,8)
    const unsigned char* vpad = (const unsigned char*)d_in[6];  // (2,96,96) bool
    float* out = (float*)d_out;                   // 600 C + 2 src + 2 tgt

    prep_kernel<<<BS*NF + BS, 96>>>(tmask, vpad);
    mask_heavy<<<BS*NF*NQ, 256>>>(masks);
    combine_kernel<<<BS*NQ, 128>>>(logits, boxes, tboxes, tvalid, out);
    argmin_kernel<<<1, 64>>>(out);
}